// round 11
// baseline (speedup 1.0000x reference)
#include <cuda_runtime.h>
#include <cuda_bf16.h>
#include <math.h>

#define N_ITER 32768
#define NB 257
#define PIANO 8388608
#define CHUNK 32
#define WARM 12
#define FPB 4        // frames per CTA in fwd
#define G_FR 16      // output frames per CTA in inv
#define ACC (G_FR * 256)

// padded shared index: break 32-float bank periodicity
#define SP(i) ((i) + ((i) >> 5))

#define GBAR(id) asm volatile("bar.sync %0, 64;" :: "r"(id) : "memory")

// Frequency-domain scratch (static __device__ arrays — no allocs allowed).
__device__ float g_ehr[N_ITER * NB];
__device__ float g_ehi[N_ITER * NB];
__device__ float g_zr[N_ITER * NB];
__device__ float g_zi[N_ITER * NB];
__device__ float g_twc[257], g_tws[257];   // e^{-i*pi*k/256}

__global__ void tw_init_kernel() {
    int k = threadIdx.x;
    if (k < 257) {
        float s, c;
        sincospif(-(float)k / 256.f, &s, &c);
        g_twc[k] = c; g_tws[k] = s;
    }
}

// ---------------------------------------------------------------------------
// Kernel 1: impulse gen + 512-pt real FFT as 256-pt complex radix-4 Stockham.
// Stage 0 fused with global load; stage 3 twiddle-free. Group-local named
// barriers decouple the 4 frames per 256-thread CTA.
// ---------------------------------------------------------------------------
__global__ void __launch_bounds__(256) fwd_kernel(const float* __restrict__ noise,
                                                  const float* __restrict__ env) {
    __shared__ float Ar[FPB][264], Ai[FPB][264], Br[FPB][264], Bi[FPB][264];
    __shared__ float twc[257], tws[257];
    int t = threadIdx.x & 63, g = threadIdx.x >> 6;
    int bid = g + 1;
    int f = blockIdx.x * FPB + g;

    { int k = threadIdx.x;
      twc[k] = g_twc[k]; tws[k] = g_tws[k];
      if (k == 0) { twc[256] = g_twc[256]; tws[256] = g_tws[256]; } }

    float e = env[f];
    float amp = e * e;
    const float2* nf2 = (const float2*)(noise + (size_t)f * 512);
    float x0r, x0i, x1r, x1i, x2r, x2i, x3r, x3i;
    { float2 v = nf2[t];       x0r = (2.f*v.x-1.f)*amp; x0i = (2.f*v.y-1.f)*amp; }
    { float2 v = nf2[t + 64];  x1r = (2.f*v.x-1.f)*amp; x1i = (2.f*v.y-1.f)*amp; }
    { float2 v = nf2[t + 128]; x2r = (2.f*v.x-1.f)*amp; x2i = (2.f*v.y-1.f)*amp; }
    { float2 v = nf2[t + 192]; x3r = (2.f*v.x-1.f)*amp; x3i = (2.f*v.y-1.f)*amp; }
    __syncthreads();   // table ready (block-wide, once)

    // Stage 0 (m=1, j=t) in registers -> A.
    {
        float t0r = x0r + x2r, t0i = x0i + x2i;
        float t1r = x0r - x2r, t1i = x0i - x2i;
        float t2r = x1r + x3r, t2i = x1i + x3i;
        float t3r = x1r - x3r, t3i = x1i - x3i;
        float y0r = t0r + t2r, y0i = t0i + t2i;
        float u1r = t1r + t3i, u1i = t1i - t3r;
        float u2r = t0r - t2r, u2i = t0i - t2i;
        float u3r = t1r - t3i, u3i = t1i + t3r;
        float w1c = twc[2 * t], w1s = tws[2 * t];
        float w2c = w1c*w1c - w1s*w1s, w2s = 2.f*w1c*w1s;
        float w3c = w2c*w1c - w2s*w1s, w3s = w2c*w1s + w2s*w1c;
        int o = 4 * t;
        Ar[g][SP(o)]   = y0r;                  Ai[g][SP(o)]   = y0i;
        Ar[g][SP(o+1)] = u1r*w1c - u1i*w1s;    Ai[g][SP(o+1)] = u1r*w1s + u1i*w1c;
        Ar[g][SP(o+2)] = u2r*w2c - u2i*w2s;    Ai[g][SP(o+2)] = u2r*w2s + u2i*w2c;
        Ar[g][SP(o+3)] = u3r*w3c - u3i*w3s;    Ai[g][SP(o+3)] = u3r*w3s + u3i*w3c;
    }
    GBAR(bid);

    // Stages 1-2 through shared (A->B->A).
#pragma unroll
    for (int r = 1; r < 3; ++r) {
        int m = 1 << (2 * r);
        int k = t & (m - 1);
        int j = t >> (2 * r);
        const float (*srcr)[264] = (r == 1) ? Ar : Br;
        const float (*srci)[264] = (r == 1) ? Ai : Bi;
        float (*dstr)[264] = (r == 1) ? Br : Ar;
        float (*dsti)[264] = (r == 1) ? Bi : Ai;
        float a0r = srcr[g][SP(t)],       a0i = srci[g][SP(t)];
        float a1r = srcr[g][SP(t + 64)],  a1i = srci[g][SP(t + 64)];
        float a2r = srcr[g][SP(t + 128)], a2i = srci[g][SP(t + 128)];
        float a3r = srcr[g][SP(t + 192)], a3i = srci[g][SP(t + 192)];
        float t0r = a0r + a2r, t0i = a0i + a2i;
        float t1r = a0r - a2r, t1i = a0i - a2i;
        float t2r = a1r + a3r, t2i = a1i + a3i;
        float t3r = a1r - a3r, t3i = a1i - a3i;
        float y0r = t0r + t2r, y0i = t0i + t2i;
        float u1r = t1r + t3i, u1i = t1i - t3r;
        float u2r = t0r - t2r, u2i = t0i - t2i;
        float u3r = t1r - t3i, u3i = t1i + t3r;
        int idx = 2 * j * m;
        float w1c = twc[idx], w1s = tws[idx];
        float w2c = w1c*w1c - w1s*w1s, w2s = 2.f*w1c*w1s;
        float w3c = w2c*w1c - w2s*w1s, w3s = w2c*w1s + w2s*w1c;
        int o = 4 * m * j + k;
        dstr[g][SP(o)]       = y0r;                  dsti[g][SP(o)]       = y0i;
        dstr[g][SP(o+m)]     = u1r*w1c - u1i*w1s;    dsti[g][SP(o+m)]     = u1r*w1s + u1i*w1c;
        dstr[g][SP(o+2*m)]   = u2r*w2c - u2i*w2s;    dsti[g][SP(o+2*m)]   = u2r*w2s + u2i*w2c;
        dstr[g][SP(o+3*m)]   = u3r*w3c - u3i*w3s;    dsti[g][SP(o+3*m)]   = u3r*w3s + u3i*w3c;
        GBAR(bid);
    }

    // Stage 3 (m=64, j=0: twiddles = 1) -> Z[t+64h] unpadded in B.
    {
        float a0r = Ar[g][SP(t)],       a0i = Ai[g][SP(t)];
        float a1r = Ar[g][SP(t + 64)],  a1i = Ai[g][SP(t + 64)];
        float a2r = Ar[g][SP(t + 128)], a2i = Ai[g][SP(t + 128)];
        float a3r = Ar[g][SP(t + 192)], a3i = Ai[g][SP(t + 192)];
        float t0r = a0r + a2r, t0i = a0i + a2i;
        float t1r = a0r - a2r, t1i = a0i - a2i;
        float t2r = a1r + a3r, t2i = a1i + a3i;
        float t3r = a1r - a3r, t3i = a1i - a3i;
        Br[g][t]       = t0r + t2r;  Bi[g][t]       = t0i + t2i;
        Br[g][t + 64]  = t1r + t3i;  Bi[g][t + 64]  = t1i - t3r;
        Br[g][t + 128] = t0r - t2r;  Bi[g][t + 128] = t0i - t2i;
        Br[g][t + 192] = t1r - t3i;  Bi[g][t + 192] = t1i + t3r;
    }
    GBAR(bid);

    // Untangle 256-pt complex FFT Z into 257-bin rfft.
    float* ehr = g_ehr + (size_t)f * NB;
    float* ehi = g_ehi + (size_t)f * NB;
#pragma unroll
    for (int h = 0; h < 4; ++h) {
        int k = t + 64 * h;
        int k2 = (256 - k) & 255;
        float Arv = Br[g][k],  Aiv = Bi[g][k];
        float Crv = Br[g][k2], Civ = Bi[g][k2];
        float Xer = 0.5f * (Arv + Crv), Xei = 0.5f * (Aiv - Civ);
        float Dr  = 0.5f * (Arv - Crv), Di  = 0.5f * (Aiv + Civ);
        float Xor = Di, Xoi = -Dr;                 // -i*D
        float c = twc[k], s = tws[k];
        ehr[k] = Xer + Xor * c - Xoi * s;
        ehi[k] = Xei + Xor * s + Xoi * c;
    }
    if (t == 0) {
        ehr[256] = Br[g][0] - Bi[g][0];
        ehi[256] = 0.f;
    }
}

// ---------------------------------------------------------------------------
// Kernel 2: chunk-parallel frequency-domain recurrence (unchanged).
// ---------------------------------------------------------------------------
__global__ void __launch_bounds__(288) recur_kernel(const float* __restrict__ tfr_g,
                                                    const float* __restrict__ tfi_g) {
    __shared__ float2 gbuf[2][260];
    int c = blockIdx.x, t = threadIdx.x;
    int start = c * CHUNK;
    int i0 = start - WARM;
    if (i0 < 0) i0 = 0;
    int end = start + CHUNK;
    bool act = (t < NB);
    int k = act ? t : 0;

    float yr = 0.f, yi = 0.f;
    float er = 0.f, ei = 0.f, tr = 0.f, ti = 0.f;
    if (act) {
        size_t b = (size_t)i0 * NB + k;
        er = g_ehr[b]; ei = g_ehi[b];
        tr = tfr_g[b]; ti = tfi_g[b];
    }
    int p = 0;
    for (int i = i0; i < end; ++i) {
        float cer = er, cei = ei, ctr = tr, cti = ti;
        if (act && (i + 1 < end)) {
            size_t b2 = (size_t)(i + 1) * NB + k;
            er = g_ehr[b2]; ei = g_ehi[b2];
            tr = tfr_g[b2]; ti = tfi_g[b2];
        }
        float zr = yr + cer, zi = yi + cei;
        if (act && i >= start - 1) {   // keep z at start-1 too (inv redundant frame)
            size_t bo = (size_t)i * NB + k;
            g_zr[bo] = zr;
            g_zi[bo] = zi;
        }
        float gr = ctr * zr - cti * zi;
        float gi = ctr * zi + cti * zr;
        if (k == 0 || k == 256) gi = 0.f;
        if (act) {
            gbuf[p][k + 1] = make_float2(gr, gi);
            if (k == 1)   gbuf[p][0]   = make_float2(gr, -gi);
            if (k == 255) gbuf[p][258] = make_float2(gr, -gi);
        }
        __syncthreads();
        if (act) {
            float2 L = gbuf[p][k];
            float2 R = gbuf[p][k + 2];
            yr = 0.54f * gr - 0.23f * (L.x + R.x);
            yi = 0.54f * gi - 0.23f * (L.y + R.y);
        }
        p ^= 1;
    }
}

// ---------------------------------------------------------------------------
// 512-pt irfft for one frame (64-thread group). Produces x[2n]+i*x[2n+1] at
// n = t+64h in v[h]. Uses group-local named barrier `bid`.
// ---------------------------------------------------------------------------
__device__ __forceinline__ void irfft512(const float* __restrict__ zr,
                                         const float* __restrict__ zi,
                                         float* __restrict__ Ar_, float* __restrict__ Ai_,
                                         float* __restrict__ Br_, float* __restrict__ Bi_,
                                         const float* __restrict__ twc,
                                         const float* __restrict__ tws,
                                         int t, int bid, float2 v[4]) {
    for (int k = t; k < 257; k += 64) { Br_[k] = zr[k]; Bi_[k] = zi[k]; }
    GBAR(bid);

    // Untangle -> Z[k] (regs) then stage 0 -> A.
    float zkr[4], zki[4];
#pragma unroll
    for (int h = 0; h < 4; ++h) {
        int k = t + 64 * h;
        float Arv = Br_[k],       Aiv = Bi_[k];
        float Crv = Br_[256 - k], Civ = Bi_[256 - k];
        float Xer = 0.5f * (Arv + Crv), Xei = 0.5f * (Aiv - Civ);
        float Dr  = 0.5f * (Arv - Crv), Di  = 0.5f * (Aiv + Civ);
        float c = twc[k], s = -tws[k];            // e^{+i*pi*k/256}
        float Xor = Dr * c - Di * s;
        float Xoi = Dr * s + Di * c;
        zkr[h] = (Xer - Xoi) * (1.f / 256.f);
        zki[h] = (Xei + Xor) * (1.f / 256.f);
    }
    {
        float t0r = zkr[0] + zkr[2], t0i = zki[0] + zki[2];
        float t1r = zkr[0] - zkr[2], t1i = zki[0] - zki[2];
        float t2r = zkr[1] + zkr[3], t2i = zki[1] + zki[3];
        float t3r = zkr[1] - zkr[3], t3i = zki[1] - zki[3];
        float y0r = t0r + t2r, y0i = t0i + t2i;
        float u1r = t1r - t3i, u1i = t1i + t3r;   // inverse orientation
        float u2r = t0r - t2r, u2i = t0i - t2i;
        float u3r = t1r + t3i, u3i = t1i - t3r;
        float w1c = twc[2 * t], w1s = -tws[2 * t];
        float w2c = w1c*w1c - w1s*w1s, w2s = 2.f*w1c*w1s;
        float w3c = w2c*w1c - w2s*w1s, w3s = w2c*w1s + w2s*w1c;
        int o = 4 * t;
        Ar_[SP(o)]   = y0r;                  Ai_[SP(o)]   = y0i;
        Ar_[SP(o+1)] = u1r*w1c - u1i*w1s;    Ai_[SP(o+1)] = u1r*w1s + u1i*w1c;
        Ar_[SP(o+2)] = u2r*w2c - u2i*w2s;    Ai_[SP(o+2)] = u2r*w2s + u2i*w2c;
        Ar_[SP(o+3)] = u3r*w3c - u3i*w3s;    Ai_[SP(o+3)] = u3r*w3s + u3i*w3c;
    }
    GBAR(bid);

    // Stages 1-2 (A->B->A), inverse twiddles.
#pragma unroll
    for (int r = 1; r < 3; ++r) {
        int m = 1 << (2 * r);
        int k = t & (m - 1);
        int j = t >> (2 * r);
        const float* sr = (r == 1) ? Ar_ : Br_;
        const float* si = (r == 1) ? Ai_ : Bi_;
        float* dr = (r == 1) ? Br_ : Ar_;
        float* di = (r == 1) ? Bi_ : Ai_;
        float a0r = sr[SP(t)],       a0i = si[SP(t)];
        float a1r = sr[SP(t + 64)],  a1i = si[SP(t + 64)];
        float a2r = sr[SP(t + 128)], a2i = si[SP(t + 128)];
        float a3r = sr[SP(t + 192)], a3i = si[SP(t + 192)];
        float t0r = a0r + a2r, t0i = a0i + a2i;
        float t1r = a0r - a2r, t1i = a0i - a2i;
        float t2r = a1r + a3r, t2i = a1i + a3i;
        float t3r = a1r - a3r, t3i = a1i - a3i;
        float y0r = t0r + t2r, y0i = t0i + t2i;
        float u1r = t1r - t3i, u1i = t1i + t3r;
        float u2r = t0r - t2r, u2i = t0i - t2i;
        float u3r = t1r + t3i, u3i = t1i - t3r;
        int idx = 2 * j * m;
        float w1c = twc[idx], w1s = -tws[idx];
        float w2c = w1c*w1c - w1s*w1s, w2s = 2.f*w1c*w1s;
        float w3c = w2c*w1c - w2s*w1s, w3s = w2c*w1s + w2s*w1c;
        int o = 4 * m * j + k;
        dr[SP(o)]       = y0r;                  di[SP(o)]       = y0i;
        dr[SP(o+m)]     = u1r*w1c - u1i*w1s;    di[SP(o+m)]     = u1r*w1s + u1i*w1c;
        dr[SP(o+2*m)]   = u2r*w2c - u2i*w2s;    di[SP(o+2*m)]   = u2r*w2s + u2i*w2c;
        dr[SP(o+3*m)]   = u3r*w3c - u3i*w3s;    di[SP(o+3*m)]   = u3r*w3s + u3i*w3c;
        GBAR(bid);
    }

    // Stage 3 (twiddle-free).
    {
        float a0r = Ar_[SP(t)],       a0i = Ai_[SP(t)];
        float a1r = Ar_[SP(t + 64)],  a1i = Ai_[SP(t + 64)];
        float a2r = Ar_[SP(t + 128)], a2i = Ai_[SP(t + 128)];
        float a3r = Ar_[SP(t + 192)], a3i = Ai_[SP(t + 192)];
        float t0r = a0r + a2r, t0i = a0i + a2i;
        float t1r = a0r - a2r, t1i = a0i - a2i;
        float t2r = a1r + a3r, t2i = a1i + a3i;
        float t3r = a1r - a3r, t3i = a1i - a3i;
        v[0] = make_float2(t0r + t2r, t0i + t2i);
        v[1] = make_float2(t1r - t3i, t1i + t3r);
        v[2] = make_float2(t0r - t2r, t0i - t2i);
        v[3] = make_float2(t1r + t3i, t1i - t3r);
    }
}

// ---------------------------------------------------------------------------
// Kernel 3: single-pass irfft + overlap-add in shared. CTA owns G_FR frames
// plus one redundant preceding frame; accumulates into shared acc (exact
// parity tilings -> race-free schedule), writes its span once, coalesced.
// ---------------------------------------------------------------------------
__global__ void __launch_bounds__(256) inv_kernel(float* __restrict__ out) {
    __shared__ float Ar[4][264], Ai[4][264], Br[4][264], Bi[4][264];
    __shared__ float twc[257], tws[257];
    __shared__ __align__(16) float acc[ACC];   // 16B-aligned: copied out as float4
    int t = threadIdx.x & 63, g = threadIdx.x >> 6;
    int bid = g + 1;
    int f0 = blockIdx.x * G_FR;

    { int k = threadIdx.x;
      twc[k] = g_twc[k]; tws[k] = g_tws[k];
      if (k == 0) { twc[256] = g_twc[256]; tws[256] = g_tws[256]; } }
    __syncthreads();

    // Rounds: evens (write, exact tiles) then odds (add). q=-1 -> group idle.
    const int qs[5][4] = {{0, 2, 4, 6}, {8, 10, 12, 14}, {16, 1, 3, 5},
                          {7, 9, 11, 13}, {15, -1, -1, -1}};
#pragma unroll 1
    for (int r = 0; r < 5; ++r) {
        int q = qs[r][g];
        if (q >= 0) {
            int f = f0 - 1 + q;
            float2 v[4];
            if (f < 0) {
                v[0] = v[1] = v[2] = v[3] = make_float2(0.f, 0.f);
            } else {
                irfft512(g_zr + (size_t)f * NB, g_zi + (size_t)f * NB,
                         Ar[g], Ai[g], Br[g], Bi[g], twc, tws, t, bid, v);
            }
            bool wr = ((q & 1) == 0);
            int base = (q - 1) * 256;
#pragma unroll
            for (int h = 0; h < 4; ++h) {
                int s = base + 2 * (t + 64 * h);
                if (s >= 0 && s < ACC) {
                    if (wr) { acc[s] = v[h].x;  acc[s + 1] = v[h].y; }
                    else    { acc[s] += v[h].x; acc[s + 1] += v[h].y; }
                }
            }
        }
        __syncthreads();
    }

    // Coalesced write-only output of this CTA's span.
    float4* o4 = (float4*)(out + (size_t)f0 * 256);
    const float4* a4 = (const float4*)acc;
#pragma unroll
    for (int i = threadIdx.x; i < ACC / 4; i += 256) o4[i] = a4[i];
}

// ---------------------------------------------------------------------------
extern "C" void kernel_launch(void* const* d_in, const int* in_sizes, int n_in,
                              void* d_out, int out_size) {
    const float* noise = nullptr;
    const float* env = nullptr;
    const float* tfr = nullptr;
    const float* tfi = nullptr;
    for (int i = 0; i < n_in; ++i) {
        if (in_sizes[i] == 16777216) noise = (const float*)d_in[i];          // [32768, 512]
        else if (in_sizes[i] == 32770) env = (const float*)d_in[i];          // [32770]
        else if (in_sizes[i] == 8421890) {                                   // [32770, 257] x2
            if (!tfr) tfr = (const float*)d_in[i];
            else      tfi = (const float*)d_in[i];
        }
    }
    float* out = (float*)d_out;

    tw_init_kernel<<<1, 288>>>();
    fwd_kernel<<<N_ITER / FPB, 256>>>(noise, env);
    recur_kernel<<<N_ITER / CHUNK, 288>>>(tfr, tfi);
    inv_kernel<<<N_ITER / G_FR, 256>>>(out);
}

// round 13
// speedup vs baseline: 1.0382x; 1.0382x over previous
#include <cuda_runtime.h>
#include <cuda_bf16.h>
#include <math.h>

#define N_ITER 32768
#define NB 257
#define PIANO 8388608
#define CHUNK 32
#define WARM 12
#define FPB 4        // frames per CTA in fwd and inv

// padded shared index: break 32-float bank periodicity
#define SP(i) ((i) + ((i) >> 5))

#define GBAR(id) asm volatile("bar.sync %0, 64;" :: "r"(id) : "memory")

// Frequency-domain scratch (static __device__ arrays — no allocs allowed).
__device__ float g_ehr[N_ITER * NB];
__device__ float g_ehi[N_ITER * NB];
__device__ float g_zr[N_ITER * NB];
__device__ float g_zi[N_ITER * NB];
__device__ float g_twc[257], g_tws[257];   // e^{-i*pi*k/256}

__global__ void tw_init_kernel() {
    int k = threadIdx.x;
    if (k < 257) {
        float s, c;
        sincospif(-(float)k / 256.f, &s, &c);
        g_twc[k] = c; g_tws[k] = s;
    }
}

// Zero the output buffer (REDG accumulates into it; re-zeroed every call).
__global__ void __launch_bounds__(256) zero_kernel(float4* __restrict__ out4) {
    int i = blockIdx.x * 256 + threadIdx.x;
    out4[i] = make_float4(0.f, 0.f, 0.f, 0.f);
}

// ---------------------------------------------------------------------------
// Kernel 1: impulse gen + 512-pt real FFT as 256-pt complex radix-4 Stockham.
// Stage 0 fused with global load; stage 3 twiddle-free. Group-local named
// barriers decouple the 4 frames per 256-thread CTA.
// ---------------------------------------------------------------------------
__global__ void __launch_bounds__(256) fwd_kernel(const float* __restrict__ noise,
                                                  const float* __restrict__ env) {
    __shared__ float Ar[FPB][264], Ai[FPB][264], Br[FPB][264], Bi[FPB][264];
    __shared__ float twc[257], tws[257];
    int t = threadIdx.x & 63, g = threadIdx.x >> 6;
    int bid = g + 1;
    int f = blockIdx.x * FPB + g;

    { int k = threadIdx.x;
      twc[k] = g_twc[k]; tws[k] = g_tws[k];
      if (k == 0) { twc[256] = g_twc[256]; tws[256] = g_tws[256]; } }

    float e = env[f];
    float amp = e * e;
    const float2* nf2 = (const float2*)(noise + (size_t)f * 512);
    float x0r, x0i, x1r, x1i, x2r, x2i, x3r, x3i;
    { float2 v = nf2[t];       x0r = (2.f*v.x-1.f)*amp; x0i = (2.f*v.y-1.f)*amp; }
    { float2 v = nf2[t + 64];  x1r = (2.f*v.x-1.f)*amp; x1i = (2.f*v.y-1.f)*amp; }
    { float2 v = nf2[t + 128]; x2r = (2.f*v.x-1.f)*amp; x2i = (2.f*v.y-1.f)*amp; }
    { float2 v = nf2[t + 192]; x3r = (2.f*v.x-1.f)*amp; x3i = (2.f*v.y-1.f)*amp; }
    __syncthreads();   // table ready (block-wide, once)

    // Stage 0 (m=1, j=t) in registers -> A.
    {
        float t0r = x0r + x2r, t0i = x0i + x2i;
        float t1r = x0r - x2r, t1i = x0i - x2i;
        float t2r = x1r + x3r, t2i = x1i + x3i;
        float t3r = x1r - x3r, t3i = x1i - x3i;
        float y0r = t0r + t2r, y0i = t0i + t2i;
        float u1r = t1r + t3i, u1i = t1i - t3r;
        float u2r = t0r - t2r, u2i = t0i - t2i;
        float u3r = t1r - t3i, u3i = t1i + t3r;
        float w1c = twc[2 * t], w1s = tws[2 * t];
        float w2c = w1c*w1c - w1s*w1s, w2s = 2.f*w1c*w1s;
        float w3c = w2c*w1c - w2s*w1s, w3s = w2c*w1s + w2s*w1c;
        int o = 4 * t;
        Ar[g][SP(o)]   = y0r;                  Ai[g][SP(o)]   = y0i;
        Ar[g][SP(o+1)] = u1r*w1c - u1i*w1s;    Ai[g][SP(o+1)] = u1r*w1s + u1i*w1c;
        Ar[g][SP(o+2)] = u2r*w2c - u2i*w2s;    Ai[g][SP(o+2)] = u2r*w2s + u2i*w2c;
        Ar[g][SP(o+3)] = u3r*w3c - u3i*w3s;    Ai[g][SP(o+3)] = u3r*w3s + u3i*w3c;
    }
    GBAR(bid);

    // Stages 1-2 through shared (A->B->A).
#pragma unroll
    for (int r = 1; r < 3; ++r) {
        int m = 1 << (2 * r);
        int k = t & (m - 1);
        int j = t >> (2 * r);
        const float (*srcr)[264] = (r == 1) ? Ar : Br;
        const float (*srci)[264] = (r == 1) ? Ai : Bi;
        float (*dstr)[264] = (r == 1) ? Br : Ar;
        float (*dsti)[264] = (r == 1) ? Bi : Ai;
        float a0r = srcr[g][SP(t)],       a0i = srci[g][SP(t)];
        float a1r = srcr[g][SP(t + 64)],  a1i = srci[g][SP(t + 64)];
        float a2r = srcr[g][SP(t + 128)], a2i = srci[g][SP(t + 128)];
        float a3r = srcr[g][SP(t + 192)], a3i = srci[g][SP(t + 192)];
        float t0r = a0r + a2r, t0i = a0i + a2i;
        float t1r = a0r - a2r, t1i = a0i - a2i;
        float t2r = a1r + a3r, t2i = a1i + a3i;
        float t3r = a1r - a3r, t3i = a1i - a3i;
        float y0r = t0r + t2r, y0i = t0i + t2i;
        float u1r = t1r + t3i, u1i = t1i - t3r;
        float u2r = t0r - t2r, u2i = t0i - t2i;
        float u3r = t1r - t3i, u3i = t1i + t3r;
        int idx = 2 * j * m;
        float w1c = twc[idx], w1s = tws[idx];
        float w2c = w1c*w1c - w1s*w1s, w2s = 2.f*w1c*w1s;
        float w3c = w2c*w1c - w2s*w1s, w3s = w2c*w1s + w2s*w1c;
        int o = 4 * m * j + k;
        dstr[g][SP(o)]       = y0r;                  dsti[g][SP(o)]       = y0i;
        dstr[g][SP(o+m)]     = u1r*w1c - u1i*w1s;    dsti[g][SP(o+m)]     = u1r*w1s + u1i*w1c;
        dstr[g][SP(o+2*m)]   = u2r*w2c - u2i*w2s;    dsti[g][SP(o+2*m)]   = u2r*w2s + u2i*w2c;
        dstr[g][SP(o+3*m)]   = u3r*w3c - u3i*w3s;    dsti[g][SP(o+3*m)]   = u3r*w3s + u3i*w3c;
        GBAR(bid);
    }

    // Stage 3 (m=64, j=0: twiddles = 1) -> Z[t+64h] unpadded in B.
    {
        float a0r = Ar[g][SP(t)],       a0i = Ai[g][SP(t)];
        float a1r = Ar[g][SP(t + 64)],  a1i = Ai[g][SP(t + 64)];
        float a2r = Ar[g][SP(t + 128)], a2i = Ai[g][SP(t + 128)];
        float a3r = Ar[g][SP(t + 192)], a3i = Ai[g][SP(t + 192)];
        float t0r = a0r + a2r, t0i = a0i + a2i;
        float t1r = a0r - a2r, t1i = a0i - a2i;
        float t2r = a1r + a3r, t2i = a1i + a3i;
        float t3r = a1r - a3r, t3i = a1i - a3i;
        Br[g][t]       = t0r + t2r;  Bi[g][t]       = t0i + t2i;
        Br[g][t + 64]  = t1r + t3i;  Bi[g][t + 64]  = t1i - t3r;
        Br[g][t + 128] = t0r - t2r;  Bi[g][t + 128] = t0i - t2i;
        Br[g][t + 192] = t1r - t3i;  Bi[g][t + 192] = t1i + t3r;
    }
    GBAR(bid);

    // Untangle 256-pt complex FFT Z into 257-bin rfft.
    float* ehr = g_ehr + (size_t)f * NB;
    float* ehi = g_ehi + (size_t)f * NB;
#pragma unroll
    for (int h = 0; h < 4; ++h) {
        int k = t + 64 * h;
        int k2 = (256 - k) & 255;
        float Arv = Br[g][k],  Aiv = Bi[g][k];
        float Crv = Br[g][k2], Civ = Bi[g][k2];
        float Xer = 0.5f * (Arv + Crv), Xei = 0.5f * (Aiv - Civ);
        float Dr  = 0.5f * (Arv - Crv), Di  = 0.5f * (Aiv + Civ);
        float Xor = Di, Xoi = -Dr;                 // -i*D
        float c = twc[k], s = tws[k];
        ehr[k] = Xer + Xor * c - Xoi * s;
        ehi[k] = Xei + Xor * s + Xoi * c;
    }
    if (t == 0) {
        ehr[256] = Br[g][0] - Bi[g][0];
        ehi[256] = 0.f;
    }
}

// ---------------------------------------------------------------------------
// Kernel 2: chunk-parallel frequency-domain recurrence (unchanged).
// ---------------------------------------------------------------------------
__global__ void __launch_bounds__(288) recur_kernel(const float* __restrict__ tfr_g,
                                                    const float* __restrict__ tfi_g) {
    __shared__ float2 gbuf[2][260];
    int c = blockIdx.x, t = threadIdx.x;
    int start = c * CHUNK;
    int i0 = start - WARM;
    if (i0 < 0) i0 = 0;
    int end = start + CHUNK;
    bool act = (t < NB);
    int k = act ? t : 0;

    float yr = 0.f, yi = 0.f;
    float er = 0.f, ei = 0.f, tr = 0.f, ti = 0.f;
    if (act) {
        size_t b = (size_t)i0 * NB + k;
        er = g_ehr[b]; ei = g_ehi[b];
        tr = tfr_g[b]; ti = tfi_g[b];
    }
    int p = 0;
    for (int i = i0; i < end; ++i) {
        float cer = er, cei = ei, ctr = tr, cti = ti;
        if (act && (i + 1 < end)) {
            size_t b2 = (size_t)(i + 1) * NB + k;
            er = g_ehr[b2]; ei = g_ehi[b2];
            tr = tfr_g[b2]; ti = tfi_g[b2];
        }
        float zr = yr + cer, zi = yi + cei;
        if (act && i >= start) {
            size_t bo = (size_t)i * NB + k;
            g_zr[bo] = zr;
            g_zi[bo] = zi;
        }
        float gr = ctr * zr - cti * zi;
        float gi = ctr * zi + cti * zr;
        if (k == 0 || k == 256) gi = 0.f;
        if (act) {
            gbuf[p][k + 1] = make_float2(gr, gi);
            if (k == 1)   gbuf[p][0]   = make_float2(gr, -gi);
            if (k == 255) gbuf[p][258] = make_float2(gr, -gi);
        }
        __syncthreads();
        if (act) {
            float2 L = gbuf[p][k];
            float2 R = gbuf[p][k + 2];
            yr = 0.54f * gr - 0.23f * (L.x + R.x);
            yi = 0.54f * gi - 0.23f * (L.y + R.y);
        }
        p ^= 1;
    }
}

// ---------------------------------------------------------------------------
// 512-pt irfft for one frame (64-thread group). Produces x[2n]+i*x[2n+1] at
// n = t+64h in v[h]. Uses group-local named barrier `bid`.
// ---------------------------------------------------------------------------
__device__ __forceinline__ void irfft512(const float* __restrict__ zr,
                                         const float* __restrict__ zi,
                                         float* __restrict__ Ar_, float* __restrict__ Ai_,
                                         float* __restrict__ Br_, float* __restrict__ Bi_,
                                         const float* __restrict__ twc,
                                         const float* __restrict__ tws,
                                         int t, int bid, float2 v[4]) {
    for (int k = t; k < 257; k += 64) { Br_[k] = zr[k]; Bi_[k] = zi[k]; }
    GBAR(bid);

    // Untangle -> Z[k] (regs) then stage 0 -> A.
    float zkr[4], zki[4];
#pragma unroll
    for (int h = 0; h < 4; ++h) {
        int k = t + 64 * h;
        float Arv = Br_[k],       Aiv = Bi_[k];
        float Crv = Br_[256 - k], Civ = Bi_[256 - k];
        float Xer = 0.5f * (Arv + Crv), Xei = 0.5f * (Aiv - Civ);
        float Dr  = 0.5f * (Arv - Crv), Di  = 0.5f * (Aiv + Civ);
        float c = twc[k], s = -tws[k];            // e^{+i*pi*k/256}
        float Xor = Dr * c - Di * s;
        float Xoi = Dr * s + Di * c;
        zkr[h] = (Xer - Xoi) * (1.f / 256.f);
        zki[h] = (Xei + Xor) * (1.f / 256.f);
    }
    {
        float t0r = zkr[0] + zkr[2], t0i = zki[0] + zki[2];
        float t1r = zkr[0] - zkr[2], t1i = zki[0] - zki[2];
        float t2r = zkr[1] + zkr[3], t2i = zki[1] + zki[3];
        float t3r = zkr[1] - zkr[3], t3i = zki[1] - zki[3];
        float y0r = t0r + t2r, y0i = t0i + t2i;
        float u1r = t1r - t3i, u1i = t1i + t3r;   // inverse orientation
        float u2r = t0r - t2r, u2i = t0i - t2i;
        float u3r = t1r + t3i, u3i = t1i - t3r;
        float w1c = twc[2 * t], w1s = -tws[2 * t];
        float w2c = w1c*w1c - w1s*w1s, w2s = 2.f*w1c*w1s;
        float w3c = w2c*w1c - w2s*w1s, w3s = w2c*w1s + w2s*w1c;
        int o = 4 * t;
        Ar_[SP(o)]   = y0r;                  Ai_[SP(o)]   = y0i;
        Ar_[SP(o+1)] = u1r*w1c - u1i*w1s;    Ai_[SP(o+1)] = u1r*w1s + u1i*w1c;
        Ar_[SP(o+2)] = u2r*w2c - u2i*w2s;    Ai_[SP(o+2)] = u2r*w2s + u2i*w2c;
        Ar_[SP(o+3)] = u3r*w3c - u3i*w3s;    Ai_[SP(o+3)] = u3r*w3s + u3i*w3c;
    }
    GBAR(bid);

    // Stages 1-2 (A->B->A), inverse twiddles.
#pragma unroll
    for (int r = 1; r < 3; ++r) {
        int m = 1 << (2 * r);
        int k = t & (m - 1);
        int j = t >> (2 * r);
        const float* sr = (r == 1) ? Ar_ : Br_;
        const float* si = (r == 1) ? Ai_ : Bi_;
        float* dr = (r == 1) ? Br_ : Ar_;
        float* di = (r == 1) ? Bi_ : Ai_;
        float a0r = sr[SP(t)],       a0i = si[SP(t)];
        float a1r = sr[SP(t + 64)],  a1i = si[SP(t + 64)];
        float a2r = sr[SP(t + 128)], a2i = si[SP(t + 128)];
        float a3r = sr[SP(t + 192)], a3i = si[SP(t + 192)];
        float t0r = a0r + a2r, t0i = a0i + a2i;
        float t1r = a0r - a2r, t1i = a0i - a2i;
        float t2r = a1r + a3r, t2i = a1i + a3i;
        float t3r = a1r - a3r, t3i = a1i - a3i;
        float y0r = t0r + t2r, y0i = t0i + t2i;
        float u1r = t1r - t3i, u1i = t1i + t3r;
        float u2r = t0r - t2r, u2i = t0i - t2i;
        float u3r = t1r + t3i, u3i = t1i - t3r;
        int idx = 2 * j * m;
        float w1c = twc[idx], w1s = -tws[idx];
        float w2c = w1c*w1c - w1s*w1s, w2s = 2.f*w1c*w1s;
        float w3c = w2c*w1c - w2s*w1s, w3s = w2c*w1s + w2s*w1c;
        int o = 4 * m * j + k;
        dr[SP(o)]       = y0r;                  di[SP(o)]       = y0i;
        dr[SP(o+m)]     = u1r*w1c - u1i*w1s;    di[SP(o+m)]     = u1r*w1s + u1i*w1c;
        dr[SP(o+2*m)]   = u2r*w2c - u2i*w2s;    di[SP(o+2*m)]   = u2r*w2s + u2i*w2c;
        dr[SP(o+3*m)]   = u3r*w3c - u3i*w3s;    di[SP(o+3*m)]   = u3r*w3s + u3i*w3c;
        GBAR(bid);
    }

    // Stage 3 (twiddle-free).
    {
        float a0r = Ar_[SP(t)],       a0i = Ai_[SP(t)];
        float a1r = Ar_[SP(t + 64)],  a1i = Ai_[SP(t + 64)];
        float a2r = Ar_[SP(t + 128)], a2i = Ai_[SP(t + 128)];
        float a3r = Ar_[SP(t + 192)], a3i = Ai_[SP(t + 192)];
        float t0r = a0r + a2r, t0i = a0i + a2i;
        float t1r = a0r - a2r, t1i = a0i - a2i;
        float t2r = a1r + a3r, t2i = a1i + a3i;
        float t3r = a1r - a3r, t3i = a1i - a3i;
        v[0] = make_float2(t0r + t2r, t0i + t2i);
        v[1] = make_float2(t1r - t3i, t1i + t3r);
        v[2] = make_float2(t0r - t2r, t0i - t2i);
        v[3] = make_float2(t1r + t3i, t1i - t3r);
    }
}

// ---------------------------------------------------------------------------
// Kernel 3: single-pass irfft + overlap-add via red.global (no-return atomic
// adds into the zeroed output). Each frame FFT'd exactly once; every output
// sample receives exactly 2 commutative float adds -> deterministic. No block
// syncs in the FFT path; 4 independent 64-thread groups per CTA.
// ---------------------------------------------------------------------------
__global__ void __launch_bounds__(256) inv_kernel(float* __restrict__ out) {
    __shared__ float Ar[FPB][264], Ai[FPB][264], Br[FPB][264], Bi[FPB][264];
    __shared__ float twc[257], tws[257];
    int t = threadIdx.x & 63, g = threadIdx.x >> 6;
    int bid = g + 1;
    int f = blockIdx.x * FPB + g;

    { int k = threadIdx.x;
      twc[k] = g_twc[k]; tws[k] = g_tws[k];
      if (k == 0) { twc[256] = g_twc[256]; tws[256] = g_tws[256]; } }
    __syncthreads();

    float2 v[4];
    irfft512(g_zr + (size_t)f * NB, g_zi + (size_t)f * NB,
             Ar[g], Ai[g], Br[g], Bi[g], twc, tws, t, bid, v);

    size_t base = (size_t)f * 256;
#pragma unroll
    for (int h = 0; h < 4; ++h) {
        int n = t + 64 * h;
        size_t s = base + 2 * (size_t)n;
        if (s + 1 < (size_t)PIANO) {   // clips only frame 32767's second half
            asm volatile("red.global.add.f32 [%0], %1;"
                         :: "l"(out + s), "f"(v[h].x) : "memory");
            asm volatile("red.global.add.f32 [%0], %1;"
                         :: "l"(out + s + 1), "f"(v[h].y) : "memory");
        }
    }
}

// ---------------------------------------------------------------------------
extern "C" void kernel_launch(void* const* d_in, const int* in_sizes, int n_in,
                              void* d_out, int out_size) {
    const float* noise = nullptr;
    const float* env = nullptr;
    const float* tfr = nullptr;
    const float* tfi = nullptr;
    for (int i = 0; i < n_in; ++i) {
        if (in_sizes[i] == 16777216) noise = (const float*)d_in[i];          // [32768, 512]
        else if (in_sizes[i] == 32770) env = (const float*)d_in[i];          // [32770]
        else if (in_sizes[i] == 8421890) {                                   // [32770, 257] x2
            if (!tfr) tfr = (const float*)d_in[i];
            else      tfi = (const float*)d_in[i];
        }
    }
    float* out = (float*)d_out;

    tw_init_kernel<<<1, 288>>>();
    zero_kernel<<<PIANO / (4 * 256), 256>>>((float4*)out);
    fwd_kernel<<<N_ITER / FPB, 256>>>(noise, env);
    recur_kernel<<<N_ITER / CHUNK, 288>>>(tfr, tfi);
    inv_kernel<<<N_ITER / FPB, 256>>>(out);
}